// round 13
// baseline (speedup 1.0000x reference)
#include <cuda_runtime.h>
#include <cuda_fp16.h>
#include <cfloat>
#include <cstdint>

// Shapes: enc (32,64,64,64) fp32 -> 131072 vectors D=64; codebook (512,64) fp32.
#define DDIM    64
#define KCODE   512
#define NTOT    8388608
#define NVEC    131072
#define TPB     384
#define GRID    148
#define N32     3584               // 32-row units (rows 0..114687)
#define N16     1024               // 16-row tail units (rows 114688..131071)
#define NUNITS  (N32 + N16)        // 4608

// SMEM: B fragments (512 codes x 256B: h|m interleaved) + esq
#define B_BYTES   (KCODE * 256)          // 131072
#define ESQ_OFF   B_BYTES
#define SMEM_TOTAL (ESQ_OFF + 2048)      // 133120

__device__ double       g_loss = 0.0;
__device__ unsigned int g_unit = 0;
__device__ unsigned int g_done = 0;

__device__ __forceinline__ void mma_f16(float c[4], const unsigned a[4],
                                        unsigned b0, unsigned b1) {
    asm volatile(
        "mma.sync.aligned.m16n8k16.row.col.f32.f16.f16.f32 "
        "{%0,%1,%2,%3}, {%4,%5,%6,%7}, {%8,%9}, {%0,%1,%2,%3};"
        : "+f"(c[0]), "+f"(c[1]), "+f"(c[2]), "+f"(c[3])
        : "r"(a[0]), "r"(a[1]), "r"(a[2]), "r"(a[3]), "r"(b0), "r"(b1));
}

// fp32 -> 2x fp16 split: h+m == f up to ~2^-24 rel (residual covered by recheck)
__device__ __forceinline__ void split2(float f, unsigned short& h, unsigned short& m) {
    __half hh = __float2half_rn(f);
    float r = f - __half2float(hh);
    __half hm = __float2half_rn(r);
    h = __half_as_ushort(hh);
    m = __half_as_ushort(hm);
}
__device__ __forceinline__ unsigned pk(unsigned short a, unsigned short b) {
    return (unsigned)a | ((unsigned)b << 16);
}

// monotone fp32 -> u32 key, low 9 bits replaced by code index
__device__ __forceinline__ unsigned dkey(float f, int code) {
    unsigned bits = __float_as_uint(f);
    unsigned msk = (unsigned)(((int)bits) >> 31);
    unsigned sk = bits ^ (msk | 0x80000000u);
    return (sk & 0xFFFFFE00u) | (unsigned)code;
}
// merge two sorted (b1<=b2) top-2 key pairs
__device__ __forceinline__ void mrg2(unsigned& a1, unsigned& a2,
                                     unsigned b1, unsigned b2) {
    unsigned t = umax(a1, b1);
    a1 = umin(a1, b1);
    a2 = umin(t, umin(a2, b2));
}

// load one A tile (rows r, r+8 per lane) into h/m fragments
__device__ __forceinline__ void load_a_tile(const float* __restrict__ p0,
                                            int q, unsigned aH[4][4],
                                            unsigned aM[4][4]) {
    const float* p1 = p0 + 8 * DDIM;
#pragma unroll
    for (int ks = 0; ks < 4; ks++) {
        const int c0 = 16 * ks + 2 * q;
        float2 x0a = *(const float2*)(p0 + c0);
        float2 x0b = *(const float2*)(p0 + c0 + 8);
        float2 x1a = *(const float2*)(p1 + c0);
        float2 x1b = *(const float2*)(p1 + c0 + 8);
        unsigned short h0,m0, h1,m1;
        split2(x0a.x, h0, m0); split2(x0a.y, h1, m1);
        aH[ks][0] = pk(h0,h1); aM[ks][0] = pk(m0,m1);
        split2(x1a.x, h0, m0); split2(x1a.y, h1, m1);
        aH[ks][1] = pk(h0,h1); aM[ks][1] = pk(m0,m1);
        split2(x0b.x, h0, m0); split2(x0b.y, h1, m1);
        aH[ks][2] = pk(h0,h1); aM[ks][2] = pk(m0,m1);
        split2(x1b.x, h0, m0); split2(x1b.y, h1, m1);
        aH[ks][3] = pk(h0,h1); aM[ks][3] = pk(m0,m1);
    }
}

__global__ __launch_bounds__(TPB, 1)
void vq_mma_kernel(const float* __restrict__ enc,
                   const float* __restrict__ embed,
                   float* __restrict__ out,
                   int out_size) {
    extern __shared__ unsigned char sraw[];
    float* s_esq = (float*)(sraw + ESQ_OFF);

    const int tid  = threadIdx.x;
    const int lane = tid & 31;
    const int rq   = lane >> 2;   // row-in-group 0..7
    const int q    = lane & 3;    // col-group 0..3

    // ---- one-time: codebook -> interleaved h|m fragment SMEM (-2*e) + esq
    for (int n = tid; n < KCODE; n += TPB) {
        const float4* g4 = (const float4*)(embed + (size_t)n * DDIM);
        float esq = 0.f;
        unsigned char* brow = sraw + (size_t)n * 256;
#pragma unroll
        for (int ks = 0; ks < 4; ks++) {
            float f[16];
#pragma unroll
            for (int i = 0; i < 4; i++) {
                float4 t = g4[ks * 4 + i];
                f[4*i+0] = t.x; f[4*i+1] = t.y; f[4*i+2] = t.z; f[4*i+3] = t.w;
            }
            unsigned short h[16], m[16];
#pragma unroll
            for (int i = 0; i < 16; i++) {
                esq += f[i] * f[i];
                split2(-2.0f * f[i], h[i], m[i]);
            }
            unsigned rot = ((unsigned)(ks + n) & 3u) * 64u;
#pragma unroll
            for (int qq = 0; qq < 4; qq++) {
                int k0 = 2 * qq;
                *(uint4*)(brow + rot + qq * 16) =
                    make_uint4(pk(h[k0], h[k0+1]), pk(h[k0+8], h[k0+9]),
                               pk(m[k0], m[k0+1]), pk(m[k0+8], m[k0+9]));
            }
        }
        s_esq[n] = esq;
    }
    __syncthreads();

    float lsum = 0.f;

    // ---- per-warp hierarchical work-stealing: 32-row units, then 16-row tail
    for (;;) {
        unsigned u;
        if (lane == 0) u = atomicAdd(&g_unit, 1u);
        u = __shfl_sync(0xffffffffu, u, 0);
        if (u >= NUNITS) break;
        const bool two = (u < N32);
        const int base = two ? (int)u * 32 : N32 * 32 + ((int)u - N32) * 16;

        // ---- A fragments
        unsigned a0H[4][4], a0M[4][4], a1H[4][4], a1M[4][4];
        load_a_tile(enc + (size_t)(base + rq) * DDIM, q, a0H, a0M);
        if (two) load_a_tile(enc + (size_t)(base + 16 + rq) * DDIM, q, a1H, a1M);

        unsigned kb1[4], kb2[4];
#pragma unroll
        for (int i = 0; i < 4; i++) { kb1[i] = 0xFFFFFFFFu; kb2[i] = 0xFFFFFFFFu; }

#pragma unroll 1
        for (int chunk = 0; chunk < 16; chunk++) {   // 32 codes per chunk
            float c0[4][4], c1[4][4];
#pragma unroll
            for (int nf = 0; nf < 4; nf++) {
                int n0 = chunk * 32 + nf * 8 + 2 * q;
                float2 e2 = *(const float2*)(s_esq + n0);
                c0[nf][0] = e2.x; c0[nf][1] = e2.y;
                c0[nf][2] = e2.x; c0[nf][3] = e2.y;
                c1[nf][0] = e2.x; c1[nf][1] = e2.y;
                c1[nf][2] = e2.x; c1[nf][3] = e2.y;
            }
#pragma unroll
            for (int ks = 0; ks < 4; ks++) {
                const unsigned rot = (((unsigned)ks + (unsigned)rq) & 3u) * 64u;
                const unsigned char* bp =
                    sraw + ((size_t)(chunk * 32 + rq)) * 256 + rot + (unsigned)q * 16u;
#pragma unroll
                for (int nf = 0; nf < 4; nf++) {
                    uint4 b = *(const uint4*)(bp + nf * 2048);
                    mma_f16(c0[nf], a0H[ks], b.x, b.y);   // hh
                    mma_f16(c0[nf], a0H[ks], b.z, b.w);   // hm
                    mma_f16(c0[nf], a0M[ks], b.x, b.y);   // mh
                    if (two) {
                        mma_f16(c1[nf], a1H[ks], b.x, b.y);
                        mma_f16(c1[nf], a1H[ks], b.z, b.w);
                        mma_f16(c1[nf], a1M[ks], b.x, b.y);
                    }
                }
            }
            // packed-key top-2 trees
#pragma unroll
            for (int s = 0; s < 2; s++) {
                unsigned l1[4], l2[4];
#pragma unroll
                for (int nf = 0; nf < 4; nf++) {
                    int n0 = chunk * 32 + nf * 8 + 2 * q;
                    unsigned ka = dkey(c0[nf][2*s],   n0);
                    unsigned kc = dkey(c0[nf][2*s+1], n0 + 1);
                    l1[nf] = umin(ka, kc); l2[nf] = umax(ka, kc);
                }
                mrg2(l1[0], l2[0], l1[1], l2[1]);
                mrg2(l1[2], l2[2], l1[3], l2[3]);
                mrg2(l1[0], l2[0], l1[2], l2[2]);
                mrg2(kb1[s], kb2[s], l1[0], l2[0]);
            }
            if (two) {
#pragma unroll
                for (int s = 0; s < 2; s++) {
                    unsigned l1[4], l2[4];
#pragma unroll
                    for (int nf = 0; nf < 4; nf++) {
                        int n0 = chunk * 32 + nf * 8 + 2 * q;
                        unsigned ka = dkey(c1[nf][2*s],   n0);
                        unsigned kc = dkey(c1[nf][2*s+1], n0 + 1);
                        l1[nf] = umin(ka, kc); l2[nf] = umax(ka, kc);
                    }
                    mrg2(l1[0], l2[0], l1[1], l2[1]);
                    mrg2(l1[2], l2[2], l1[3], l2[3]);
                    mrg2(l1[0], l2[0], l1[2], l2[2]);
                    mrg2(kb1[2 + s], kb2[2 + s], l1[0], l2[0]);
                }
            }
        }

        // ---- merge top-2 across the 4 lanes sharing rows
#pragma unroll
        for (int off = 1; off <= 2; off <<= 1) {
#pragma unroll
            for (int j = 0; j < 4; j++) {
                unsigned o1 = __shfl_xor_sync(0xffffffffu, kb1[j], off);
                unsigned o2 = __shfl_xor_sync(0xffffffffu, kb2[j], off);
                mrg2(kb1[j], kb2[j], o1, o2);
            }
        }

        int i1[4];
#pragma unroll
        for (int j = 0; j < 4; j++) i1[j] = (int)(kb1[j] & 0x1FFu);

        if (q == 0) {
            // ---- exact recheck when key gap <= 1 quantum
#pragma unroll
            for (int j = 0; j < 4; j++) {
                if (j >= (two ? 4 : 2)) break;
                unsigned k1 = kb1[j], k2 = kb2[j];
                const int row = base + (j >> 1) * 16 + (j & 1) * 8 + rq;
                if ((k2 >> 9) - (k1 >> 9) <= 1u) {
                    int a = (int)(k1 & 0x1FFu), b = (int)(k2 & 0x1FFu);
                    const float* xp  = enc + (size_t)row * DDIM;
                    const float* e1p = embed + (size_t)a * DDIM;
                    const float* e2p = embed + (size_t)b * DDIM;
                    double d1 = 0.0, d2 = 0.0;
#pragma unroll 8
                    for (int d = 0; d < DDIM; d++) {
                        double xv = xp[d];
                        double t1 = xv - (double)e1p[d];
                        double t2 = xv - (double)e2p[d];
                        d1 += t1 * t1; d2 += t2 * t2;
                    }
                    i1[j] = (d2 < d1 || (d2 == d1 && b < a)) ? b : a;
                }
                if (out_size >= NTOT + 1 + NVEC)
                    out[NTOT + 1 + row] = (float)i1[j];
            }
        }

        // ---- gather + write quantized + exact loss
        if (two) {
            // lane owns full row base+lane
            const int r = lane;
            const int src = 4 * (r & 7);
            int s0 = __shfl_sync(0xffffffffu, i1[0], src);
            int s1 = __shfl_sync(0xffffffffu, i1[1], src);
            int s2 = __shfl_sync(0xffffffffu, i1[2], src);
            int s3 = __shfl_sync(0xffffffffu, i1[3], src);
            const int b = (r < 8) ? s0 : (r < 16) ? s1 : (r < 24) ? s2 : s3;
            const float4* ep = (const float4*)(embed + (size_t)b * DDIM);
            const float4* xp = (const float4*)(enc + (size_t)(base + r) * DDIM);
            float4* op = (float4*)(out + (size_t)(base + r) * DDIM);
#pragma unroll
            for (int i = 0; i < 16; i++) {
                float4 e = ep[i];
                float4 x = xp[i];
                float d0 = e.x - x.x, d1 = e.y - x.y, d2 = e.z - x.z, d3 = e.w - x.w;
                lsum += d0 * d0 + d1 * d1 + d2 * d2 + d3 * d3;
                op[i] = e;
            }
        } else {
            // lane handles row (lane&15), half (lane>>4)
            const int r    = lane & 15;
            const int half = lane >> 4;
            const int src  = 4 * (r & 7);
            int s0 = __shfl_sync(0xffffffffu, i1[0], src);
            int s1 = __shfl_sync(0xffffffffu, i1[1], src);
            const int b = (r < 8) ? s0 : s1;
            const float4* ep = (const float4*)(embed + (size_t)b * DDIM + half * 32);
            const float4* xp = (const float4*)(enc + (size_t)(base + r) * DDIM + half * 32);
            float4* op = (float4*)(out + (size_t)(base + r) * DDIM + half * 32);
#pragma unroll
            for (int i = 0; i < 8; i++) {
                float4 e = ep[i];
                float4 x = xp[i];
                float d0 = e.x - x.x, d1 = e.y - x.y, d2 = e.z - x.z, d3 = e.w - x.w;
                lsum += d0 * d0 + d1 * d1 + d2 * d2 + d3 * d3;
                op[i] = e;
            }
        }
    }

    // ---- loss reduce -> global
    double ls = (double)lsum;
#pragma unroll
    for (int off = 16; off > 0; off >>= 1)
        ls += __shfl_down_sync(0xffffffffu, ls, off);
    if (lane == 0) atomicAdd(&g_loss, ls);

    __syncthreads();
    if (tid == 0) {
        __threadfence();
        unsigned done = atomicAdd(&g_done, 1u);
        if (done == GRID - 1) {
            unsigned long long bits =
                atomicExch((unsigned long long*)&g_loss, 0ull);
            double total = __longlong_as_double((long long)bits);
            if (out_size >= NTOT + 1)
                out[NTOT] = (float)(2.0 * total / (double)NTOT);
            atomicExch(&g_unit, 0u);
            atomicExch(&g_done, 0u);
        }
    }
}

extern "C" void kernel_launch(void* const* d_in, const int* in_sizes, int n_in,
                              void* d_out, int out_size) {
    const float* enc   = (const float*)d_in[0];
    const float* embed = (const float*)d_in[1];
    float* out = (float*)d_out;

    static bool attr_set = false;
    if (!attr_set) {
        cudaFuncSetAttribute(vq_mma_kernel,
                             cudaFuncAttributeMaxDynamicSharedMemorySize,
                             SMEM_TOTAL);
        attr_set = true;
    }

    vq_mma_kernel<<<GRID, TPB, SMEM_TOTAL>>>(enc, embed, out, out_size);
}

// round 14
// speedup vs baseline: 1.0184x; 1.0184x over previous
#include <cuda_runtime.h>
#include <cuda_fp16.h>
#include <cfloat>
#include <cstdint>

// Shapes: enc (32,64,64,64) fp32 -> 131072 vectors D=64; codebook (512,64) fp32.
#define DDIM    64
#define KCODE   512
#define NTOT    8388608
#define NVEC    131072
#define TPB     512
#define GRID    148
#define N32     3584               // 32-row units (rows 0..114687)
#define N16     1024               // 16-row tail units (rows 114688..131071)
#define NUNITS  (N32 + N16)        // 4608

// SMEM: B fragments (512 codes x 256B: h|m interleaved) + esq
#define B_BYTES   (KCODE * 256)          // 131072
#define ESQ_OFF   B_BYTES
#define SMEM_TOTAL (ESQ_OFF + 2048)      // 133120

__device__ double       g_loss = 0.0;
__device__ unsigned int g_unit = 0;
__device__ unsigned int g_done = 0;

__device__ __forceinline__ void mma_f16(float c[4], const unsigned a[4],
                                        unsigned b0, unsigned b1) {
    asm volatile(
        "mma.sync.aligned.m16n8k16.row.col.f32.f16.f16.f32 "
        "{%0,%1,%2,%3}, {%4,%5,%6,%7}, {%8,%9}, {%0,%1,%2,%3};"
        : "+f"(c[0]), "+f"(c[1]), "+f"(c[2]), "+f"(c[3])
        : "r"(a[0]), "r"(a[1]), "r"(a[2]), "r"(a[3]), "r"(b0), "r"(b1));
}

// fp32 -> 2x fp16 split: h+m == f up to ~2^-24 rel (residual covered by recheck)
__device__ __forceinline__ void split2(float f, unsigned short& h, unsigned short& m) {
    __half hh = __float2half_rn(f);
    float r = f - __half2float(hh);
    __half hm = __float2half_rn(r);
    h = __half_as_ushort(hh);
    m = __half_as_ushort(hm);
}
__device__ __forceinline__ unsigned pk(unsigned short a, unsigned short b) {
    return (unsigned)a | ((unsigned)b << 16);
}

// monotone fp32 -> u32 key, low 9 bits replaced by code index
__device__ __forceinline__ unsigned dkey(float f, int code) {
    unsigned bits = __float_as_uint(f);
    unsigned msk = (unsigned)(((int)bits) >> 31);
    unsigned sk = bits ^ (msk | 0x80000000u);
    return (sk & 0xFFFFFE00u) | (unsigned)code;
}
// merge two sorted (b1<=b2) top-2 key pairs
__device__ __forceinline__ void mrg2(unsigned& a1, unsigned& a2,
                                     unsigned b1, unsigned b2) {
    unsigned t = umax(a1, b1);
    a1 = umin(a1, b1);
    a2 = umin(t, umin(a2, b2));
}

// load one A tile (rows r, r+8 per lane) into h/m fragments
__device__ __forceinline__ void load_a_tile(const float* __restrict__ p0,
                                            int q, unsigned aH[4][4],
                                            unsigned aM[4][4]) {
    const float* p1 = p0 + 8 * DDIM;
#pragma unroll
    for (int ks = 0; ks < 4; ks++) {
        const int c0 = 16 * ks + 2 * q;
        float2 x0a = *(const float2*)(p0 + c0);
        float2 x0b = *(const float2*)(p0 + c0 + 8);
        float2 x1a = *(const float2*)(p1 + c0);
        float2 x1b = *(const float2*)(p1 + c0 + 8);
        unsigned short h0,m0, h1,m1;
        split2(x0a.x, h0, m0); split2(x0a.y, h1, m1);
        aH[ks][0] = pk(h0,h1); aM[ks][0] = pk(m0,m1);
        split2(x1a.x, h0, m0); split2(x1a.y, h1, m1);
        aH[ks][1] = pk(h0,h1); aM[ks][1] = pk(m0,m1);
        split2(x0b.x, h0, m0); split2(x0b.y, h1, m1);
        aH[ks][2] = pk(h0,h1); aM[ks][2] = pk(m0,m1);
        split2(x1b.x, h0, m0); split2(x1b.y, h1, m1);
        aH[ks][3] = pk(h0,h1); aM[ks][3] = pk(m0,m1);
    }
}

__global__ __launch_bounds__(TPB, 1)
void vq_mma_kernel(const float* __restrict__ enc,
                   const float* __restrict__ embed,
                   float* __restrict__ out,
                   int out_size) {
    extern __shared__ unsigned char sraw[];
    float* s_esq = (float*)(sraw + ESQ_OFF);

    const int tid  = threadIdx.x;
    const int lane = tid & 31;
    const int rq   = lane >> 2;   // row-in-group 0..7
    const int q    = lane & 3;    // col-group 0..3

    // ---- one-time: codebook -> interleaved h|m fragment SMEM (-2*e) + esq
    for (int n = tid; n < KCODE; n += TPB) {
        const float4* g4 = (const float4*)(embed + (size_t)n * DDIM);
        float esq = 0.f;
        unsigned char* brow = sraw + (size_t)n * 256;
#pragma unroll
        for (int ks = 0; ks < 4; ks++) {
            float f[16];
#pragma unroll
            for (int i = 0; i < 4; i++) {
                float4 t = g4[ks * 4 + i];
                f[4*i+0] = t.x; f[4*i+1] = t.y; f[4*i+2] = t.z; f[4*i+3] = t.w;
            }
            unsigned short h[16], m[16];
#pragma unroll
            for (int i = 0; i < 16; i++) {
                esq += f[i] * f[i];
                split2(-2.0f * f[i], h[i], m[i]);
            }
            unsigned rot = ((unsigned)(ks + n) & 3u) * 64u;
#pragma unroll
            for (int qq = 0; qq < 4; qq++) {
                int k0 = 2 * qq;
                *(uint4*)(brow + rot + qq * 16) =
                    make_uint4(pk(h[k0], h[k0+1]), pk(h[k0+8], h[k0+9]),
                               pk(m[k0], m[k0+1]), pk(m[k0+8], m[k0+9]));
            }
        }
        s_esq[n] = esq;
    }
    __syncthreads();

    float lsum = 0.f;

    // ---- per-warp hierarchical work-stealing: 32-row units, then 16-row tail
    for (;;) {
        unsigned u;
        if (lane == 0) u = atomicAdd(&g_unit, 1u);
        u = __shfl_sync(0xffffffffu, u, 0);
        if (u >= NUNITS) break;
        const bool two = (u < N32);
        const int base = two ? (int)u * 32 : N32 * 32 + ((int)u - N32) * 16;

        // ---- A fragments
        unsigned a0H[4][4], a0M[4][4], a1H[4][4], a1M[4][4];
        load_a_tile(enc + (size_t)(base + rq) * DDIM, q, a0H, a0M);
        if (two) load_a_tile(enc + (size_t)(base + 16 + rq) * DDIM, q, a1H, a1M);

        unsigned kb1[4], kb2[4];
#pragma unroll
        for (int i = 0; i < 4; i++) { kb1[i] = 0xFFFFFFFFu; kb2[i] = 0xFFFFFFFFu; }

#pragma unroll 1
        for (int chunk = 0; chunk < 64; chunk++) {   // 8 codes per chunk
            const int n0 = chunk * 8 + 2 * q;
            float2 e2 = *(const float2*)(s_esq + n0);
            float c0[4], c1[4];
            c0[0] = e2.x; c0[1] = e2.y; c0[2] = e2.x; c0[3] = e2.y;
            c1[0] = e2.x; c1[1] = e2.y; c1[2] = e2.x; c1[3] = e2.y;

            const unsigned char* brow =
                sraw + ((size_t)(chunk * 8 + rq)) * 256 + (unsigned)q * 16u;
#pragma unroll
            for (int ks = 0; ks < 4; ks++) {
                const unsigned rot = (((unsigned)ks + (unsigned)rq) & 3u) * 64u;
                uint4 b = *(const uint4*)(brow + rot);
                mma_f16(c0, a0H[ks], b.x, b.y);   // hh
                mma_f16(c0, a0H[ks], b.z, b.w);   // hm
                mma_f16(c0, a0M[ks], b.x, b.y);   // mh
                if (two) {
                    mma_f16(c1, a1H[ks], b.x, b.y);
                    mma_f16(c1, a1H[ks], b.z, b.w);
                    mma_f16(c1, a1M[ks], b.x, b.y);
                }
            }
            // packed-key top-2 (parallel IMNMX)
#pragma unroll
            for (int s = 0; s < 2; s++) {
                unsigned ka = dkey(c0[2*s],   n0);
                unsigned kc = dkey(c0[2*s+1], n0 + 1);
                mrg2(kb1[s], kb2[s], umin(ka, kc), umax(ka, kc));
            }
            if (two) {
#pragma unroll
                for (int s = 0; s < 2; s++) {
                    unsigned ka = dkey(c1[2*s],   n0);
                    unsigned kc = dkey(c1[2*s+1], n0 + 1);
                    mrg2(kb1[2 + s], kb2[2 + s], umin(ka, kc), umax(ka, kc));
                }
            }
        }

        // ---- merge top-2 across the 4 lanes sharing rows
#pragma unroll
        for (int off = 1; off <= 2; off <<= 1) {
#pragma unroll
            for (int j = 0; j < 4; j++) {
                unsigned o1 = __shfl_xor_sync(0xffffffffu, kb1[j], off);
                unsigned o2 = __shfl_xor_sync(0xffffffffu, kb2[j], off);
                mrg2(kb1[j], kb2[j], o1, o2);
            }
        }

        int i1[4];
#pragma unroll
        for (int j = 0; j < 4; j++) i1[j] = (int)(kb1[j] & 0x1FFu);

        if (q == 0) {
            // ---- exact recheck when key gap <= 1 quantum
            const int jmax = two ? 4 : 2;
#pragma unroll
            for (int j = 0; j < 4; j++) {
                if (j >= jmax) break;
                unsigned k1 = kb1[j], k2 = kb2[j];
                const int row = base + (j >> 1) * 16 + (j & 1) * 8 + rq;
                if ((k2 >> 9) - (k1 >> 9) <= 1u) {
                    int a = (int)(k1 & 0x1FFu), b = (int)(k2 & 0x1FFu);
                    const float* xp  = enc + (size_t)row * DDIM;
                    const float* e1p = embed + (size_t)a * DDIM;
                    const float* e2p = embed + (size_t)b * DDIM;
                    double d1 = 0.0, d2 = 0.0;
#pragma unroll 8
                    for (int d = 0; d < DDIM; d++) {
                        double xv = xp[d];
                        double t1 = xv - (double)e1p[d];
                        double t2 = xv - (double)e2p[d];
                        d1 += t1 * t1; d2 += t2 * t2;
                    }
                    i1[j] = (d2 < d1 || (d2 == d1 && b < a)) ? b : a;
                }
                if (out_size >= NTOT + 1 + NVEC)
                    out[NTOT + 1 + row] = (float)i1[j];
            }
        }

        // ---- gather + write quantized + exact loss
        if (two) {
            const int r = lane;                 // lane owns full row base+lane
            const int src = 4 * (r & 7);
            int s0 = __shfl_sync(0xffffffffu, i1[0], src);
            int s1 = __shfl_sync(0xffffffffu, i1[1], src);
            int s2 = __shfl_sync(0xffffffffu, i1[2], src);
            int s3 = __shfl_sync(0xffffffffu, i1[3], src);
            const int b = (r < 8) ? s0 : (r < 16) ? s1 : (r < 24) ? s2 : s3;
            const float4* ep = (const float4*)(embed + (size_t)b * DDIM);
            const float4* xp = (const float4*)(enc + (size_t)(base + r) * DDIM);
            float4* op = (float4*)(out + (size_t)(base + r) * DDIM);
#pragma unroll
            for (int i = 0; i < 16; i++) {
                float4 e = ep[i];
                float4 x = xp[i];
                float d0 = e.x - x.x, d1 = e.y - x.y, d2 = e.z - x.z, d3 = e.w - x.w;
                lsum += d0 * d0 + d1 * d1 + d2 * d2 + d3 * d3;
                op[i] = e;
            }
        } else {
            const int r    = lane & 15;        // row (lane&15), half (lane>>4)
            const int half = lane >> 4;
            const int src  = 4 * (r & 7);
            int s0 = __shfl_sync(0xffffffffu, i1[0], src);
            int s1 = __shfl_sync(0xffffffffu, i1[1], src);
            const int b = (r < 8) ? s0 : s1;
            const float4* ep = (const float4*)(embed + (size_t)b * DDIM + half * 32);
            const float4* xp = (const float4*)(enc + (size_t)(base + r) * DDIM + half * 32);
            float4* op = (float4*)(out + (size_t)(base + r) * DDIM + half * 32);
#pragma unroll
            for (int i = 0; i < 8; i++) {
                float4 e = ep[i];
                float4 x = xp[i];
                float d0 = e.x - x.x, d1 = e.y - x.y, d2 = e.z - x.z, d3 = e.w - x.w;
                lsum += d0 * d0 + d1 * d1 + d2 * d2 + d3 * d3;
                op[i] = e;
            }
        }
    }

    // ---- loss reduce -> global
    double ls = (double)lsum;
#pragma unroll
    for (int off = 16; off > 0; off >>= 1)
        ls += __shfl_down_sync(0xffffffffu, ls, off);
    if (lane == 0) atomicAdd(&g_loss, ls);

    __syncthreads();
    if (tid == 0) {
        __threadfence();
        unsigned done = atomicAdd(&g_done, 1u);
        if (done == GRID - 1) {
            unsigned long long bits =
                atomicExch((unsigned long long*)&g_loss, 0ull);
            double total = __longlong_as_double((long long)bits);
            if (out_size >= NTOT + 1)
                out[NTOT] = (float)(2.0 * total / (double)NTOT);
            atomicExch(&g_unit, 0u);
            atomicExch(&g_done, 0u);
        }
    }
}

extern "C" void kernel_launch(void* const* d_in, const int* in_sizes, int n_in,
                              void* d_out, int out_size) {
    const float* enc   = (const float*)d_in[0];
    const float* embed = (const float*)d_in[1];
    float* out = (float*)d_out;

    static bool attr_set = false;
    if (!attr_set) {
        cudaFuncSetAttribute(vq_mma_kernel,
                             cudaFuncAttributeMaxDynamicSharedMemorySize,
                             SMEM_TOTAL);
        attr_set = true;
    }

    vq_mma_kernel<<<GRID, TPB, SMEM_TOTAL>>>(enc, embed, out, out_size);
}

// round 16
// speedup vs baseline: 1.0908x; 1.0711x over previous
#include <cuda_runtime.h>
#include <cuda_fp16.h>
#include <cfloat>
#include <cstdint>

// Shapes: enc (32,64,64,64) fp32 -> 131072 vectors D=64; codebook (512,64) fp32.
#define DDIM    64
#define KCODE   512
#define NTOT    8388608
#define NVEC    131072
#define TPB     512
#define GRID    148
#define NROWS   16                 // rows per warp work unit
#define NUNITS  (NVEC / NROWS)     // 8192

// SMEM: B fragments (512 codes x 256B: h|m interleaved) + esq(+1 bias)
#define B_BYTES   (KCODE * 256)          // 131072
#define ESQ_OFF   B_BYTES
#define SMEM_TOTAL (ESQ_OFF + 2048)      // 133120

__device__ double       g_loss = 0.0;
__device__ unsigned int g_unit = 0;
__device__ unsigned int g_done = 0;

__device__ __forceinline__ void mma_f16(float c[4], const unsigned a[4],
                                        unsigned b0, unsigned b1) {
    asm volatile(
        "mma.sync.aligned.m16n8k16.row.col.f32.f16.f16.f32 "
        "{%0,%1,%2,%3}, {%4,%5,%6,%7}, {%8,%9}, {%0,%1,%2,%3};"
        : "+f"(c[0]), "+f"(c[1]), "+f"(c[2]), "+f"(c[3])
        : "r"(a[0]), "r"(a[1]), "r"(a[2]), "r"(a[3]), "r"(b0), "r"(b1));
}

// fp32 -> 2x fp16 split: h+m == f up to ~2^-24 rel (residual covered by recheck)
__device__ __forceinline__ void split2(float f, unsigned short& h, unsigned short& m) {
    __half hh = __float2half_rn(f);
    float r = f - __half2float(hh);
    __half hm = __float2half_rn(r);
    h = __half_as_ushort(hh);
    m = __half_as_ushort(hm);
}
__device__ __forceinline__ unsigned pk(unsigned short a, unsigned short b) {
    return (unsigned)a | ((unsigned)b << 16);
}

// POSITIVE fp32 -> u32 key (accumulator = true ||x-e||^2 + 1 > 0), low 9 bits = idx.
__device__ __forceinline__ unsigned dkey(float f, int code) {
    return (__float_as_uint(f) & 0xFFFFFE00u) | (unsigned)code;
}
// merge two sorted (b1<=b2) top-2 key pairs
__device__ __forceinline__ void mrg2(unsigned& a1, unsigned& a2,
                                     unsigned b1, unsigned b2) {
    unsigned t = umax(a1, b1);
    a1 = umin(a1, b1);
    a2 = umin(t, umin(a2, b2));
}

__global__ __launch_bounds__(TPB, 1)
void vq_mma_kernel(const float* __restrict__ enc,
                   const float* __restrict__ embed,
                   float* __restrict__ out,
                   int out_size) {
    extern __shared__ unsigned char sraw[];
    float* s_esq = (float*)(sraw + ESQ_OFF);

    const int tid  = threadIdx.x;
    const int lane = tid & 31;
    const int rq   = lane >> 2;   // row-in-group 0..7
    const int q    = lane & 3;    // col-group 0..3

    // ---- one-time: codebook -> interleaved h|m fragment SMEM (-2*e) + biased esq
    for (int n = tid; n < KCODE; n += TPB) {
        const float4* g4 = (const float4*)(embed + (size_t)n * DDIM);
        float esq = 0.f;
        unsigned char* brow = sraw + (size_t)n * 256;
#pragma unroll
        for (int ks = 0; ks < 4; ks++) {
            float f[16];
#pragma unroll
            for (int i = 0; i < 4; i++) {
                float4 t = g4[ks * 4 + i];
                f[4*i+0] = t.x; f[4*i+1] = t.y; f[4*i+2] = t.z; f[4*i+3] = t.w;
            }
            unsigned short h[16], m[16];
#pragma unroll
            for (int i = 0; i < 16; i++) {
                esq += f[i] * f[i];
                split2(-2.0f * f[i], h[i], m[i]);
            }
            unsigned rot = ((unsigned)(ks + n) & 3u) * 64u;
#pragma unroll
            for (int qq = 0; qq < 4; qq++) {
                int k0 = 2 * qq;
                *(uint4*)(brow + rot + qq * 16) =
                    make_uint4(pk(h[k0], h[k0+1]), pk(h[k0+8], h[k0+9]),
                               pk(m[k0], m[k0+1]), pk(m[k0+8], m[k0+9]));
            }
        }
        s_esq[n] = esq + 1.0f;   // +1 bias; with +||x||^2 init => strictly positive dists
    }
    __syncthreads();

    float lsum = 0.f;

    // ---- per-warp persistent work-stealing over 16-row units
    for (;;) {
        unsigned u;
        if (lane == 0) u = atomicAdd(&g_unit, 1u);
        u = __shfl_sync(0xffffffffu, u, 0);
        if (u >= NUNITS) break;

        // ---- A fragments: rows r0 = u*16 + rq, r1 = r0 + 8 ; also row ||x||^2
        unsigned aF[2][4][4];   // [term h/m][kstep][reg]
        float sq0 = 0.f, sq1 = 0.f;
        {
            const float* p0 = enc + ((size_t)u * NROWS + rq) * DDIM;
            const float* p1 = p0 + 8 * DDIM;
#pragma unroll
            for (int ks = 0; ks < 4; ks++) {
                const int c0 = 16 * ks + 2 * q;
                float2 x0a = *(const float2*)(p0 + c0);
                float2 x0b = *(const float2*)(p0 + c0 + 8);
                float2 x1a = *(const float2*)(p1 + c0);
                float2 x1b = *(const float2*)(p1 + c0 + 8);
                sq0 += x0a.x*x0a.x + x0a.y*x0a.y + x0b.x*x0b.x + x0b.y*x0b.y;
                sq1 += x1a.x*x1a.x + x1a.y*x1a.y + x1b.x*x1b.x + x1b.y*x1b.y;
                unsigned short h0,m0, h1,m1;
                split2(x0a.x, h0, m0); split2(x0a.y, h1, m1);
                aF[0][ks][0] = pk(h0,h1); aF[1][ks][0] = pk(m0,m1);
                split2(x1a.x, h0, m0); split2(x1a.y, h1, m1);
                aF[0][ks][1] = pk(h0,h1); aF[1][ks][1] = pk(m0,m1);
                split2(x0b.x, h0, m0); split2(x0b.y, h1, m1);
                aF[0][ks][2] = pk(h0,h1); aF[1][ks][2] = pk(m0,m1);
                split2(x1b.x, h0, m0); split2(x1b.y, h1, m1);
                aF[0][ks][3] = pk(h0,h1); aF[1][ks][3] = pk(m0,m1);
            }
        }
        // full row ||x||^2 across the 4-lane group
        sq0 += __shfl_xor_sync(0xffffffffu, sq0, 1);
        sq0 += __shfl_xor_sync(0xffffffffu, sq0, 2);
        sq1 += __shfl_xor_sync(0xffffffffu, sq1, 1);
        sq1 += __shfl_xor_sync(0xffffffffu, sq1, 2);

        unsigned kb1_0 = 0xFFFFFFFFu, kb2_0 = 0xFFFFFFFFu;
        unsigned kb1_1 = 0xFFFFFFFFu, kb2_1 = 0xFFFFFFFFu;

#pragma unroll 1
        for (int chunk = 0; chunk < 8; chunk++) {
            float c[8][4];
#pragma unroll
            for (int nf = 0; nf < 8; nf++) {   // init C = ||e||^2 + 1 + ||x||^2 (per row)
                int n0 = chunk * 64 + nf * 8 + 2 * q;
                float2 e2 = *(const float2*)(s_esq + n0);
                c[nf][0] = e2.x + sq0; c[nf][1] = e2.y + sq0;
                c[nf][2] = e2.x + sq1; c[nf][3] = e2.y + sq1;
            }
            // 3-term MMA: hh, hm, mh (one LDS.128 per nf per ks); 8 independent chains
#pragma unroll
            for (int ks = 0; ks < 4; ks++) {
                const unsigned rot = (((unsigned)ks + (unsigned)rq) & 3u) * 64u;
                const unsigned char* bp =
                    sraw + ((size_t)(chunk * 64 + rq)) * 256 + rot + (unsigned)q * 16u;
#pragma unroll
                for (int nf = 0; nf < 8; nf++) {
                    uint4 b = *(const uint4*)(bp + nf * 2048);
                    mma_f16(c[nf], aF[0][ks], b.x, b.y);   // hh
                    mma_f16(c[nf], aF[0][ks], b.z, b.w);   // hm
                    mma_f16(c[nf], aF[1][ks], b.x, b.y);   // mh
                }
            }
            // packed-key top-2 trees (1-op keys, parallel IMNMX)
            unsigned l1[8], l2[8];
#pragma unroll
            for (int s = 0; s < 2; s++) {
#pragma unroll
                for (int nf = 0; nf < 8; nf++) {
                    int n0 = chunk * 64 + nf * 8 + 2 * q;
                    unsigned ka = dkey(c[nf][2*s],   n0);
                    unsigned kb = dkey(c[nf][2*s+1], n0 + 1);
                    l1[nf] = umin(ka, kb);
                    l2[nf] = umax(ka, kb);
                }
#pragma unroll
                for (int w = 4; w > 0; w >>= 1)
#pragma unroll
                    for (int i = 0; i < 8; i++)
                        if (i < w) mrg2(l1[i], l2[i], l1[i + w], l2[i + w]);
                if (s == 0) mrg2(kb1_0, kb2_0, l1[0], l2[0]);
                else        mrg2(kb1_1, kb2_1, l1[0], l2[0]);
            }
        }

        // ---- merge top-2 across the 4 lanes sharing rows
#pragma unroll
        for (int off = 1; off <= 2; off <<= 1) {
            unsigned o1 = __shfl_xor_sync(0xffffffffu, kb1_0, off);
            unsigned o2 = __shfl_xor_sync(0xffffffffu, kb2_0, off);
            mrg2(kb1_0, kb2_0, o1, o2);
            o1 = __shfl_xor_sync(0xffffffffu, kb1_1, off);
            o2 = __shfl_xor_sync(0xffffffffu, kb2_1, off);
            mrg2(kb1_1, kb2_1, o1, o2);
        }

        int i1_0 = (int)(kb1_0 & 0x1FFu);
        int i1_1 = (int)(kb1_1 & 0x1FFu);

        if (q == 0) {
            // ---- exact recheck when key gap <= 2 quanta (covers trunc + approx error)
            const int row0 = (int)u * NROWS + rq;
#pragma unroll
            for (int s = 0; s < 2; s++) {
                unsigned k1 = s ? kb1_1 : kb1_0, k2 = s ? kb2_1 : kb2_0;
                if ((k2 >> 9) - (k1 >> 9) <= 2u) {
                    int i1 = (int)(k1 & 0x1FFu), i2 = (int)(k2 & 0x1FFu);
                    const float* xp  = enc + (size_t)(row0 + 8 * s) * DDIM;
                    const float* e1p = embed + (size_t)i1 * DDIM;
                    const float* e2p = embed + (size_t)i2 * DDIM;
                    double d1 = 0.0, d2 = 0.0;
#pragma unroll 8
                    for (int d = 0; d < DDIM; d++) {
                        double xv = xp[d];
                        double t1 = xv - (double)e1p[d];
                        double t2 = xv - (double)e2p[d];
                        d1 += t1 * t1; d2 += t2 * t2;
                    }
                    int pick = (d2 < d1 || (d2 == d1 && i2 < i1)) ? i2 : i1;
                    if (s) i1_1 = pick; else i1_0 = pick;
                }
            }
            if (out_size >= NTOT + 1 + NVEC) {
                out[NTOT + 1 + row0]     = (float)i1_0;
                out[NTOT + 1 + row0 + 8] = (float)i1_1;
            }
        }

        // ---- gather + write quantized + exact loss (all lanes)
        {
            const int r    = lane & 15;
            const int half = lane >> 4;
            int src  = 4 * (r & 7);
            int from0 = __shfl_sync(0xffffffffu, i1_0, src);
            int from1 = __shfl_sync(0xffffffffu, i1_1, src);
            const int b = (r < 8) ? from0 : from1;
            const float4* ep = (const float4*)(embed + (size_t)b * DDIM + half * 32);
            const float4* xp = (const float4*)(enc +
                               ((size_t)u * NROWS + r) * DDIM + half * 32);
            float4* op = (float4*)(out + ((size_t)u * NROWS + r) * DDIM + half * 32);
#pragma unroll
            for (int i = 0; i < 8; i++) {
                float4 e = ep[i];
                float4 x = xp[i];
                float d0 = e.x - x.x, d1 = e.y - x.y, d2 = e.z - x.z, d3 = e.w - x.w;
                lsum += d0 * d0 + d1 * d1 + d2 * d2 + d3 * d3;
                op[i] = e;
            }
        }
    }

    // ---- loss reduce -> global
    double ls = (double)lsum;
#pragma unroll
    for (int off = 16; off > 0; off >>= 1)
        ls += __shfl_down_sync(0xffffffffu, ls, off);
    if (lane == 0) atomicAdd(&g_loss, ls);

    __syncthreads();
    if (tid == 0) {
        __threadfence();
        unsigned done = atomicAdd(&g_done, 1u);
        if (done == GRID - 1) {
            unsigned long long bits =
                atomicExch((unsigned long long*)&g_loss, 0ull);
            double total = __longlong_as_double((long long)bits);
            if (out_size >= NTOT + 1)
                out[NTOT] = (float)(2.0 * total / (double)NTOT);
            atomicExch(&g_unit, 0u);
            atomicExch(&g_done, 0u);
        }
    }
}

extern "C" void kernel_launch(void* const* d_in, const int* in_sizes, int n_in,
                              void* d_out, int out_size) {
    const float* enc   = (const float*)d_in[0];
    const float* embed = (const float*)d_in[1];
    float* out = (float*)d_out;

    static bool attr_set = false;
    if (!attr_set) {
        cudaFuncSetAttribute(vq_mma_kernel,
                             cudaFuncAttributeMaxDynamicSharedMemorySize,
                             SMEM_TOTAL);
        attr_set = true;
    }

    vq_mma_kernel<<<GRID, TPB, SMEM_TOTAL>>>(enc, embed, out, out_size);
}